// round 12
// baseline (speedup 1.0000x reference)
#include <cuda_runtime.h>
#include <cuda_fp16.h>
#include <cuda_fp8.h>
#include <cuda.h>
#include <cstdint>

// ---------------------------------------------------------------------------
// Shapes (fixed): x[4,2048,4096] @ W[4096,4096]^T + bias -> out[8192,4096]
// ---------------------------------------------------------------------------
static constexpr int MM = 8192;
static constexpr int NN = 4096;
static constexpr int KK = 4096;

static constexpr int TILE_M = 128;
static constexpr int TILE_N = 256;
static constexpr int KC     = 64;          // K per stage (128B rows, SW128)
static constexpr int DEPTH  = 4;           // >=3 needed to hide TMA (R7 lesson)
static constexpr int ITERS  = KK / KC;     // 64
static constexpr int NTILES = (MM / TILE_M) * (NN / TILE_N);   // 1024

static constexpr int A_ST  = TILE_M * KC * 2;   // 16384
static constexpr int B_ST  = TILE_N * KC * 2;   // 32768
static constexpr int STAGE = A_ST + B_ST;       // 49152

static constexpr int SM_STAGE0  = 1024;         // 1024-aligned for SW128
static constexpr int SMEM_BYTES = SM_STAGE0 + DEPTH * STAGE;   // 197632

static constexpr int NWARPS = 8;

// ---------------------------------------------------------------------------
// Scratch: dequantized fp16 operands (device globals per harness rules)
// ---------------------------------------------------------------------------
__device__ __align__(1024) __half g_xq[(size_t)MM * KK];   // 64 MB
__device__ __align__(1024) __half g_wq[(size_t)NN * KK];   // 32 MB

// ---------------------------------------------------------------------------
// PTX helpers (family-portable only: TMA, mbarrier, ldmatrix, mma.sync)
// ---------------------------------------------------------------------------
__device__ __forceinline__ uint32_t smem_u32(const void* p) {
    uint32_t a;
    asm("{ .reg .u64 t; cvta.to.shared.u64 t, %1; cvt.u32.u64 %0, t; }" : "=r"(a) : "l"(p));
    return a;
}
__device__ __forceinline__ void mbar_init(uint32_t a, uint32_t cnt) {
    asm volatile("mbarrier.init.shared.b64 [%0], %1;" :: "r"(a), "r"(cnt) : "memory");
}
__device__ __forceinline__ void mbar_expect_tx(uint32_t a, uint32_t bytes) {
    asm volatile("mbarrier.arrive.expect_tx.shared.b64 _, [%0], %1;" :: "r"(a), "r"(bytes) : "memory");
}
__device__ __forceinline__ void mbar_arrive(uint32_t a) {
    asm volatile("mbarrier.arrive.shared.b64 _, [%0];" :: "r"(a) : "memory");
}
__device__ __forceinline__ void mbar_wait(uint32_t a, uint32_t ph) {
    asm volatile(
        "{\n\t.reg .pred P;\n"
        "LW_%=:\n\t"
        "mbarrier.try_wait.parity.acquire.cta.shared::cta.b64 P, [%0], %1, 0x989680;\n\t"
        "@P bra LD_%=;\n\t"
        "bra LW_%=;\n"
        "LD_%=:\n\t}"
        :: "r"(a), "r"(ph) : "memory");
}
__device__ __forceinline__ void mbar_wait_relaxed(uint32_t a, uint32_t ph) {
    asm volatile(
        "{\n\t.reg .pred P;\n"
        "LW_%=:\n\t"
        "mbarrier.try_wait.parity.relaxed.cta.shared::cta.b64 P, [%0], %1, 0x989680;\n\t"
        "@P bra LD_%=;\n\t"
        "bra LW_%=;\n"
        "LD_%=:\n\t}"
        :: "r"(a), "r"(ph) : "memory");
}
__device__ __forceinline__ void tma2d(uint32_t dst, const CUtensorMap* m, int cx, int cy, uint32_t bar) {
    asm volatile(
        "cp.async.bulk.tensor.2d.shared::cta.global.tile.mbarrier::complete_tx::bytes "
        "[%0], [%1, {%2, %3}], [%4];"
        :: "r"(dst), "l"(m), "r"(cx), "r"(cy), "r"(bar) : "memory");
}
__device__ __forceinline__ void fence_proxy_async_s() {
    asm volatile("fence.proxy.async.shared::cta;" ::: "memory");
}
__device__ __forceinline__ void ldsm_x4(uint32_t* r, uint32_t addr) {
    asm volatile("ldmatrix.sync.aligned.m8n8.x4.shared.b16 {%0,%1,%2,%3}, [%4];"
                 : "=r"(r[0]), "=r"(r[1]), "=r"(r[2]), "=r"(r[3]) : "r"(addr));
}
__device__ __forceinline__ void mma16816(float* c, const uint32_t* a, const uint32_t* b) {
    asm volatile(
        "mma.sync.aligned.m16n8k16.row.col.f32.f16.f16.f32 "
        "{%0,%1,%2,%3}, {%4,%5,%6,%7}, {%8,%9}, {%0,%1,%2,%3};"
        : "+f"(c[0]), "+f"(c[1]), "+f"(c[2]), "+f"(c[3])
        : "r"(a[0]), "r"(a[1]), "r"(a[2]), "r"(a[3]), "r"(b[0]), "r"(b[1]));
}

// tile id -> (m0, n0) with groups-of-8-M swizzle (L2 locality)
__device__ __forceinline__ void tile_coords(int t, int& m0, int& n0) {
    const int TIG = 8 * (NN / TILE_N);    // 128
    int grp = t / TIG, rem = t % TIG;
    m0 = (grp * 8 + (rem & 7)) * TILE_M;
    n0 = (rem >> 3) * TILE_N;
}

// ---------------------------------------------------------------------------
// Kernel 1: fused fp8-e4m3 group(32) pseudo-quantize of BOTH tensors
// thread = 16 consecutive elems; 1 div + 1 rcp per group
// ---------------------------------------------------------------------------
__device__ __forceinline__ float f8_rt(float x, float inv, float scale) {
    __nv_fp8_storage_t q = __nv_cvt_float_to_fp8(x * inv, __NV_SATFINITE, __NV_E4M3);
    __half_raw hr = __nv_cvt_fp8_to_halfraw(q, __NV_E4M3);
    return __half2float(__half(hr)) * scale;
}

__device__ __forceinline__ uint32_t rt2(float a, float b, float inv, float scale) {
    __half2 h = __halves2half2(__float2half_rn(f8_rt(a, inv, scale)),
                               __float2half_rn(f8_rt(b, inv, scale)));
    return *reinterpret_cast<uint32_t*>(&h);
}

__global__ void __launch_bounds__(256) quant_deq_fused(const float* __restrict__ x,
                                                       __half* __restrict__ dx, int nx16,
                                                       const float* __restrict__ w,
                                                       __half* __restrict__ dw, int nw16) {
    int t = blockIdx.x * 256 + threadIdx.x;
    const float* src;
    __half* dst;
    int idx;
    if (t < nx16) { src = x; dst = dx; idx = t; }
    else if (t < nx16 + nw16) { src = w; dst = dw; idx = t - nx16; }
    else return;

    const float4* s4 = reinterpret_cast<const float4*>(src) + (size_t)idx * 4;
    float4 v0 = s4[0];
    float4 v1 = s4[1];
    float4 v2 = s4[2];
    float4 v3 = s4[3];

    float m0 = fmaxf(fmaxf(fabsf(v0.x), fabsf(v0.y)), fmaxf(fabsf(v0.z), fabsf(v0.w)));
    float m1 = fmaxf(fmaxf(fabsf(v1.x), fabsf(v1.y)), fmaxf(fabsf(v1.z), fabsf(v1.w)));
    float m2 = fmaxf(fmaxf(fabsf(v2.x), fabsf(v2.y)), fmaxf(fabsf(v2.z), fabsf(v2.w)));
    float m3 = fmaxf(fmaxf(fabsf(v3.x), fabsf(v3.y)), fmaxf(fabsf(v3.z), fabsf(v3.w)));
    float amax = fmaxf(fmaxf(m0, m1), fmaxf(m2, m3));
    amax = fmaxf(amax, __shfl_xor_sync(0xffffffffu, amax, 1));
    float scale = __fdiv_rn(fmaxf(amax, 1e-8f), 448.0f);
    float inv   = __frcp_rn(scale);

    uint4 o0, o1;
    o0.x = rt2(v0.x, v0.y, inv, scale);
    o0.y = rt2(v0.z, v0.w, inv, scale);
    o0.z = rt2(v1.x, v1.y, inv, scale);
    o0.w = rt2(v1.z, v1.w, inv, scale);
    o1.x = rt2(v2.x, v2.y, inv, scale);
    o1.y = rt2(v2.z, v2.w, inv, scale);
    o1.z = rt2(v3.x, v3.y, inv, scale);
    o1.w = rt2(v3.z, v3.w, inv, scale);

    uint4* d4 = reinterpret_cast<uint4*>(dst) + (size_t)idx * 2;
    d4[0] = o0;
    d4[1] = o1;
}

// ---------------------------------------------------------------------------
// Kernel 2: PERSISTENT mma.sync fp16 GEMM  out = A @ B^T + bias
// grid = #SMs; each CTA processes tiles bid, bid+grid, ... with ONE
// continuously-warm TMA pipeline (producer prefetches across tile boundaries)
// 256 threads = 8 warps, warp tile 64x64, DEPTH=4 ring
// ---------------------------------------------------------------------------
__global__ void __launch_bounds__(256, 1) gemm_hmma_kernel(
    const __grid_constant__ CUtensorMap tma_a,
    const __grid_constant__ CUtensorMap tma_b,
    const float* __restrict__ bias,
    float* __restrict__ out) {
    extern __shared__ char smem[];
    const uint32_t sb = smem_u32(smem);
    const int tid  = threadIdx.x;
    const int lane = tid & 31;
    const int wid  = tid >> 5;
    const int wm   = wid & 1;    // 0..1 (64-row half)
    const int wn   = wid >> 1;   // 0..3 (64-col quarter)
    const int bid  = blockIdx.x;
    const int stride = gridDim.x;

    // barriers: full[s] @ sb+16s, empty[s] @ sb+16s+8
    if (tid == 0) {
        #pragma unroll
        for (int s = 0; s < DEPTH; s++) {
            mbar_init(sb + 16 * s, 1);            // full: expect_tx + tx
            mbar_init(sb + 16 * s + 8, NWARPS);   // empty: one arrive per warp
        }
        fence_proxy_async_s();
    }
    __syncthreads();

    const CUtensorMap* pa = &tma_a;
    const CUtensorMap* pb = &tma_b;

    // my total stage count (flattened over my tiles)
    const int my_tiles = (NTILES - bid + stride - 1) / stride;
    if (my_tiles <= 0) return;
    const long total = (long)my_tiles * ITERS;

    // producer state (only meaningful on tid 0)
    long pg  = 0;          // next global stage to issue
    int  pt  = bid;        // tile id of stage pg
    int  pit = 0;          // k-iteration of stage pg

    if (tid == 0) {
        asm volatile("prefetch.tensormap [%0];" :: "l"(pa));
        asm volatile("prefetch.tensormap [%0];" :: "l"(pb));
        // prologue: fill DEPTH-1 stages
        for (; pg < (total < DEPTH - 1 ? total : (long)(DEPTH - 1)); pg++) {
            int s = (int)(pg % DEPTH);
            int pm0, pn0;
            tile_coords(pt, pm0, pn0);
            mbar_expect_tx(sb + 16 * s, STAGE);
            uint32_t dst = sb + SM_STAGE0 + s * STAGE;
            tma2d(dst, pa, pit * KC, pm0, sb + 16 * s);
            tma2d(dst + A_ST, pb, pit * KC, pn0, sb + 16 * s);
            if (++pit == ITERS) { pit = 0; pt += stride; }
        }
    }

    // ---- per-thread swizzled ldmatrix base offsets ----
    uint32_t aR[4], aSX[4];
    const uint32_t aQ = ((lane >> 4) & 1) * 16;
    #pragma unroll
    for (int mi = 0; mi < 4; mi++) {
        uint32_t row = wm * 64 + mi * 16 + (lane & 15);
        aR[mi]  = row * 128;
        aSX[mi] = (aR[mi] >> 3) & 0x70;
    }
    uint32_t bR[4], bSX[4];
    const uint32_t bQ = ((lane >> 3) & 1) * 16;
    #pragma unroll
    for (int j = 0; j < 4; j++) {
        uint32_t row = wn * 64 + j * 16 + (lane & 7) + ((lane >> 4) & 1) * 8;
        bR[j]  = row * 128;
        bSX[j] = (bR[j] >> 3) & 0x70;
    }

    float c[4][8][4];
    long g = 0;   // consumer global stage counter

    for (int t = bid; t < NTILES; t += stride) {
        int m0, n0;
        tile_coords(t, m0, n0);

        #pragma unroll
        for (int mi = 0; mi < 4; mi++)
            #pragma unroll
            for (int nj = 0; nj < 8; nj++)
                #pragma unroll
                for (int k = 0; k < 4; k++) c[mi][nj][k] = 0.f;

        for (int it = 0; it < ITERS; ++it, ++g) {
            int s = (int)(g % DEPTH);
            // producer: keep DEPTH-1 stages in flight (crosses tile boundaries)
            if (tid == 0 && pg < total) {
                int ps = (int)(pg % DEPTH);
                long pv = pg / DEPTH;
                if (pv >= 1)
                    mbar_wait_relaxed(sb + 16 * ps + 8, (uint32_t)((pv - 1) & 1));
                int pm0, pn0;
                tile_coords(pt, pm0, pn0);
                mbar_expect_tx(sb + 16 * ps, STAGE);
                uint32_t dst = sb + SM_STAGE0 + ps * STAGE;
                tma2d(dst, pa, pit * KC, pm0, sb + 16 * ps);
                tma2d(dst + A_ST, pb, pit * KC, pn0, sb + 16 * ps);
                if (++pit == ITERS) { pit = 0; pt += stride; }
                pg++;
            }
            mbar_wait(sb + 16 * s, (uint32_t)((g / DEPTH) & 1));

            const uint32_t aS = sb + SM_STAGE0 + s * STAGE;
            const uint32_t bS = aS + A_ST;
            #pragma unroll
            for (int kk = 0; kk < KC / 16; ++kk) {
                uint32_t a[4][4], b[4][4];
                const uint32_t ck = (uint32_t)(kk * 32);
                #pragma unroll
                for (int mi = 0; mi < 4; mi++)
                    ldsm_x4(a[mi], aS + aR[mi] + ((ck | aQ) ^ aSX[mi]));
                #pragma unroll
                for (int j = 0; j < 4; j++)
                    ldsm_x4(b[j], bS + bR[j] + ((ck | bQ) ^ bSX[j]));
                // early empty-arrive after last smem reads of this stage
                if (kk == KC / 16 - 1 && lane == 0)
                    mbar_arrive(sb + 16 * s + 8);
                #pragma unroll
                for (int mi = 0; mi < 4; mi++)
                    #pragma unroll
                    for (int nj = 0; nj < 8; nj++)
                        mma16816(c[mi][nj], a[mi], &b[nj >> 1][(nj & 1) * 2]);
            }
        }

        // ---- per-tile epilogue: bias + fire-and-forget float2 stores ----
        const int cbase = n0 + wn * 64 + (lane & 3) * 2;
        #pragma unroll
        for (int nj = 0; nj < 8; nj++) {
            const int col = cbase + nj * 8;
            const float2 bv = *reinterpret_cast<const float2*>(&bias[col]);
            #pragma unroll
            for (int mi = 0; mi < 4; mi++) {
                const int row = m0 + wm * 64 + mi * 16 + (lane >> 2);
                float2 v0 = {c[mi][nj][0] + bv.x, c[mi][nj][1] + bv.y};
                float2 v1 = {c[mi][nj][2] + bv.x, c[mi][nj][3] + bv.y};
                *reinterpret_cast<float2*>(&out[(size_t)row * NN + col])       = v0;
                *reinterpret_cast<float2*>(&out[(size_t)(row + 8) * NN + col]) = v1;
            }
        }
    }
}

// ---------------------------------------------------------------------------
// Host launcher
// ---------------------------------------------------------------------------
typedef CUresult (*PFN_encodeTiled)(CUtensorMap*, CUtensorMapDataType, cuuint32_t, void*,
                                    const cuuint64_t*, const cuuint64_t*, const cuuint32_t*,
                                    const cuuint32_t*, CUtensorMapInterleave, CUtensorMapSwizzle,
                                    CUtensorMapL2promotion, CUtensorMapFloatOOBfill);

extern "C" void kernel_launch(void* const* d_in, const int* in_sizes, int n_in,
                              void* d_out, int out_size) {
    if (n_in < 3) return;
    const float* x    = (const float*)d_in[0];
    const float* W    = (const float*)d_in[1];
    const float* bias = (const float*)d_in[2];
    float* out = (float*)d_out;

    void* pA = nullptr;
    void* pB = nullptr;
    cudaGetSymbolAddress(&pA, g_xq);
    cudaGetSymbolAddress(&pB, g_wq);

    // 1) fused fp8 roundtrip -> fp16 scratch (16 elems/thread, one launch)
    {
        int nx16 = (int)(((long long)MM * KK) / 16);   // 2097152
        int nw16 = (int)(((long long)NN * KK) / 16);   // 1048576
        int total = nx16 + nw16;
        quant_deq_fused<<<(total + 255) / 256, 256>>>(x, (__half*)pA, nx16,
                                                      W, (__half*)pB, nw16);
    }

    // 2) TMA descriptors via driver entry point (no -lcuda)
    void* fn = nullptr;
    cudaDriverEntryPointQueryResult qr;
    cudaGetDriverEntryPointByVersion("cuTensorMapEncodeTiled", &fn, 12000,
                                     cudaEnableDefault, &qr);
    if (!fn) return;
    PFN_encodeTiled encode = (PFN_encodeTiled)fn;

    CUtensorMap map_a, map_b;
    {
        cuuint64_t dims[2]    = {(cuuint64_t)KK, (cuuint64_t)MM};
        cuuint64_t strides[1] = {(cuuint64_t)KK * 2};
        cuuint32_t box[2]     = {(cuuint32_t)KC, (cuuint32_t)TILE_M};
        cuuint32_t es[2]      = {1, 1};
        if (encode(&map_a, CU_TENSOR_MAP_DATA_TYPE_FLOAT16, 2, pA, dims, strides, box, es,
                   CU_TENSOR_MAP_INTERLEAVE_NONE, CU_TENSOR_MAP_SWIZZLE_128B,
                   CU_TENSOR_MAP_L2_PROMOTION_L2_128B,
                   CU_TENSOR_MAP_FLOAT_OOB_FILL_NONE) != CUDA_SUCCESS)
            return;
    }
    {
        cuuint64_t dims[2]    = {(cuuint64_t)KK, (cuuint64_t)NN};
        cuuint64_t strides[1] = {(cuuint64_t)KK * 2};
        cuuint32_t box[2]     = {(cuuint32_t)KC, (cuuint32_t)TILE_N};
        cuuint32_t es[2]      = {1, 1};
        if (encode(&map_b, CU_TENSOR_MAP_DATA_TYPE_FLOAT16, 2, pB, dims, strides, box, es,
                   CU_TENSOR_MAP_INTERLEAVE_NONE, CU_TENSOR_MAP_SWIZZLE_128B,
                   CU_TENSOR_MAP_L2_PROMOTION_L2_128B,
                   CU_TENSOR_MAP_FLOAT_OOB_FILL_NONE) != CUDA_SUCCESS)
            return;
    }

    // 3) persistent GEMM: grid = #SMs
    int dev = 0, nsm = 148;
    cudaGetDevice(&dev);
    cudaDeviceGetAttribute(&nsm, cudaDevAttrMultiProcessorCount, dev);
    cudaFuncSetAttribute(gemm_hmma_kernel, cudaFuncAttributeMaxDynamicSharedMemorySize,
                         SMEM_BYTES);
    gemm_hmma_kernel<<<nsm, 256, SMEM_BYTES>>>(map_a, map_b, bias, out);
    (void)in_sizes; (void)out_size;
}

// round 13
// speedup vs baseline: 1.0299x; 1.0299x over previous
#include <cuda_runtime.h>
#include <cuda_fp16.h>
#include <cuda_fp8.h>
#include <cuda.h>
#include <cstdint>

// ---------------------------------------------------------------------------
// Shapes (fixed): x[4,2048,4096] @ W[4096,4096]^T + bias -> out[8192,4096]
// ---------------------------------------------------------------------------
static constexpr int MM = 8192;
static constexpr int NN = 4096;
static constexpr int KK = 4096;

static constexpr int TILE_M = 128;
static constexpr int TILE_N = 256;
static constexpr int KC     = 64;          // K per stage (128B rows, SW128)
static constexpr int DEPTH  = 4;           // >=3 needed to hide TMA (R7 lesson)
static constexpr int ITERS  = KK / KC;     // 64

static constexpr int A_ST  = TILE_M * KC * 2;   // 16384
static constexpr int B_ST  = TILE_N * KC * 2;   // 32768
static constexpr int STAGE = A_ST + B_ST;       // 49152

static constexpr int SM_STAGE0  = 1024;         // 1024-aligned for SW128
static constexpr int SMEM_BYTES = SM_STAGE0 + DEPTH * STAGE;   // 197632

static constexpr int NWARPS = 8;

// ---------------------------------------------------------------------------
// Scratch: dequantized fp16 operands (device globals per harness rules)
// ---------------------------------------------------------------------------
__device__ __align__(1024) __half g_xq[(size_t)MM * KK];   // 64 MB
__device__ __align__(1024) __half g_wq[(size_t)NN * KK];   // 32 MB

// ---------------------------------------------------------------------------
// PTX helpers (family-portable only: TMA, mbarrier, ldmatrix, mma.sync)
// ---------------------------------------------------------------------------
__device__ __forceinline__ uint32_t smem_u32(const void* p) {
    uint32_t a;
    asm("{ .reg .u64 t; cvta.to.shared.u64 t, %1; cvt.u32.u64 %0, t; }" : "=r"(a) : "l"(p));
    return a;
}
__device__ __forceinline__ void mbar_init(uint32_t a, uint32_t cnt) {
    asm volatile("mbarrier.init.shared.b64 [%0], %1;" :: "r"(a), "r"(cnt) : "memory");
}
__device__ __forceinline__ void mbar_expect_tx(uint32_t a, uint32_t bytes) {
    asm volatile("mbarrier.arrive.expect_tx.shared.b64 _, [%0], %1;" :: "r"(a), "r"(bytes) : "memory");
}
__device__ __forceinline__ void mbar_arrive(uint32_t a) {
    asm volatile("mbarrier.arrive.shared.b64 _, [%0];" :: "r"(a) : "memory");
}
__device__ __forceinline__ void mbar_wait(uint32_t a, uint32_t ph) {
    asm volatile(
        "{\n\t.reg .pred P;\n"
        "LW_%=:\n\t"
        "mbarrier.try_wait.parity.acquire.cta.shared::cta.b64 P, [%0], %1, 0x989680;\n\t"
        "@P bra LD_%=;\n\t"
        "bra LW_%=;\n"
        "LD_%=:\n\t}"
        :: "r"(a), "r"(ph) : "memory");
}
__device__ __forceinline__ void mbar_wait_relaxed(uint32_t a, uint32_t ph) {
    asm volatile(
        "{\n\t.reg .pred P;\n"
        "LW_%=:\n\t"
        "mbarrier.try_wait.parity.relaxed.cta.shared::cta.b64 P, [%0], %1, 0x989680;\n\t"
        "@P bra LD_%=;\n\t"
        "bra LW_%=;\n"
        "LD_%=:\n\t}"
        :: "r"(a), "r"(ph) : "memory");
}
__device__ __forceinline__ void tma2d(uint32_t dst, const CUtensorMap* m, int cx, int cy, uint32_t bar) {
    asm volatile(
        "cp.async.bulk.tensor.2d.shared::cta.global.tile.mbarrier::complete_tx::bytes "
        "[%0], [%1, {%2, %3}], [%4];"
        :: "r"(dst), "l"(m), "r"(cx), "r"(cy), "r"(bar) : "memory");
}
__device__ __forceinline__ void fence_proxy_async_s() {
    asm volatile("fence.proxy.async.shared::cta;" ::: "memory");
}
__device__ __forceinline__ void ldsm_x4(uint32_t* r, uint32_t addr) {
    asm volatile("ldmatrix.sync.aligned.m8n8.x4.shared.b16 {%0,%1,%2,%3}, [%4];"
                 : "=r"(r[0]), "=r"(r[1]), "=r"(r[2]), "=r"(r[3]) : "r"(addr));
}
__device__ __forceinline__ void mma16816(float* c, const uint32_t* a, const uint32_t* b) {
    asm volatile(
        "mma.sync.aligned.m16n8k16.row.col.f32.f16.f16.f32 "
        "{%0,%1,%2,%3}, {%4,%5,%6,%7}, {%8,%9}, {%0,%1,%2,%3};"
        : "+f"(c[0]), "+f"(c[1]), "+f"(c[2]), "+f"(c[3])
        : "r"(a[0]), "r"(a[1]), "r"(a[2]), "r"(a[3]), "r"(b[0]), "r"(b[1]));
}

// ---------------------------------------------------------------------------
// Kernel 1: fused fp8-e4m3 group(32) pseudo-quantize of BOTH tensors
// thread = 16 consecutive elems; 1 div + 1 rcp per group
// ---------------------------------------------------------------------------
__device__ __forceinline__ float f8_rt(float x, float inv, float scale) {
    __nv_fp8_storage_t q = __nv_cvt_float_to_fp8(x * inv, __NV_SATFINITE, __NV_E4M3);
    __half_raw hr = __nv_cvt_fp8_to_halfraw(q, __NV_E4M3);
    return __half2float(__half(hr)) * scale;
}

__device__ __forceinline__ uint32_t rt2(float a, float b, float inv, float scale) {
    __half2 h = __halves2half2(__float2half_rn(f8_rt(a, inv, scale)),
                               __float2half_rn(f8_rt(b, inv, scale)));
    return *reinterpret_cast<uint32_t*>(&h);
}

__global__ void __launch_bounds__(256) quant_deq_fused(const float* __restrict__ x,
                                                       __half* __restrict__ dx, int nx16,
                                                       const float* __restrict__ w,
                                                       __half* __restrict__ dw, int nw16) {
    int t = blockIdx.x * 256 + threadIdx.x;
    const float* src;
    __half* dst;
    int idx;
    if (t < nx16) { src = x; dst = dx; idx = t; }
    else if (t < nx16 + nw16) { src = w; dst = dw; idx = t - nx16; }
    else return;

    const float4* s4 = reinterpret_cast<const float4*>(src) + (size_t)idx * 4;
    float4 v0 = s4[0];
    float4 v1 = s4[1];
    float4 v2 = s4[2];
    float4 v3 = s4[3];

    float m0 = fmaxf(fmaxf(fabsf(v0.x), fabsf(v0.y)), fmaxf(fabsf(v0.z), fabsf(v0.w)));
    float m1 = fmaxf(fmaxf(fabsf(v1.x), fabsf(v1.y)), fmaxf(fabsf(v1.z), fabsf(v1.w)));
    float m2 = fmaxf(fmaxf(fabsf(v2.x), fabsf(v2.y)), fmaxf(fabsf(v2.z), fabsf(v2.w)));
    float m3 = fmaxf(fmaxf(fabsf(v3.x), fabsf(v3.y)), fmaxf(fabsf(v3.z), fabsf(v3.w)));
    float amax = fmaxf(fmaxf(m0, m1), fmaxf(m2, m3));
    amax = fmaxf(amax, __shfl_xor_sync(0xffffffffu, amax, 1));
    float scale = __fdiv_rn(fmaxf(amax, 1e-8f), 448.0f);
    float inv   = __frcp_rn(scale);

    uint4 o0, o1;
    o0.x = rt2(v0.x, v0.y, inv, scale);
    o0.y = rt2(v0.z, v0.w, inv, scale);
    o0.z = rt2(v1.x, v1.y, inv, scale);
    o0.w = rt2(v1.z, v1.w, inv, scale);
    o1.x = rt2(v2.x, v2.y, inv, scale);
    o1.y = rt2(v2.z, v2.w, inv, scale);
    o1.z = rt2(v3.x, v3.y, inv, scale);
    o1.w = rt2(v3.z, v3.w, inv, scale);

    uint4* d4 = reinterpret_cast<uint4*>(dst) + (size_t)idx * 2;
    d4[0] = o0;
    d4[1] = o1;
}

// ---------------------------------------------------------------------------
// Kernel 2: mma.sync fp16 GEMM  out[M,N] = A[M,K] @ B[N,K]^T + bias
// 256 threads = 8 warps, warp grid 2(M) x 4(N), warp tile 64x64
// DEPTH=4 TMA ring + REGISTER DOUBLE-BUFFERED fragments with cross-stage
// prefetch: the full-barrier wait + first LDSM of stage s+1 are issued right
// after kk=3's 32 MMAs, hiding them behind the draining tensor queue.
// ---------------------------------------------------------------------------
struct Frag {
    uint32_t a[4][4];
    uint32_t b[4][4];
};

__global__ void __launch_bounds__(256, 1) gemm_hmma_kernel(
    const __grid_constant__ CUtensorMap tma_a,
    const __grid_constant__ CUtensorMap tma_b,
    const float* __restrict__ bias,
    float* __restrict__ out) {
    extern __shared__ char smem[];
    const uint32_t sb = smem_u32(smem);
    const int tid  = threadIdx.x;
    const int lane = tid & 31;
    const int wid  = tid >> 5;
    const int wm   = wid & 1;    // 0..1 (64-row half)
    const int wn   = wid >> 1;   // 0..3 (64-col quarter)

    // Grid swizzle: groups of 8 M-tiles, N fastest (L2 locality)
    const int TILES_N = NN / TILE_N;              // 16
    const int TIG = 8 * TILES_N;                  // 128
    int bid = blockIdx.x;
    int grp = bid / TIG, rem = bid % TIG;
    const int m0 = (grp * 8 + (rem & 7)) * TILE_M;
    const int n0 = (rem >> 3) * TILE_N;

    // barriers: full[s] @ sb+16s, empty[s] @ sb+16s+8
    if (tid == 0) {
        #pragma unroll
        for (int s = 0; s < DEPTH; s++) {
            mbar_init(sb + 16 * s, 1);            // full: expect_tx + tx
            mbar_init(sb + 16 * s + 8, NWARPS);   // empty: one arrive per warp
        }
        fence_proxy_async_s();
    }
    __syncthreads();

    const CUtensorMap* pa = &tma_a;
    const CUtensorMap* pb = &tma_b;
    if (tid == 0) {
        asm volatile("prefetch.tensormap [%0];" :: "l"(pa));
        asm volatile("prefetch.tensormap [%0];" :: "l"(pb));
        #pragma unroll
        for (int s = 0; s < DEPTH - 1; s++) {
            mbar_expect_tx(sb + 16 * s, STAGE);
            uint32_t dst = sb + SM_STAGE0 + s * STAGE;
            tma2d(dst, pa, s * KC, m0, sb + 16 * s);
            tma2d(dst + A_ST, pb, s * KC, n0, sb + 16 * s);
        }
    }

    // ---- per-thread swizzled ldmatrix base offsets ----
    uint32_t aR[4], aSX[4];
    const uint32_t aQ = ((lane >> 4) & 1) * 16;
    #pragma unroll
    for (int mi = 0; mi < 4; mi++) {
        uint32_t row = wm * 64 + mi * 16 + (lane & 15);
        aR[mi]  = row * 128;
        aSX[mi] = (aR[mi] >> 3) & 0x70;
    }
    uint32_t bR[4], bSX[4];
    const uint32_t bQ = ((lane >> 3) & 1) * 16;
    #pragma unroll
    for (int j = 0; j < 4; j++) {
        uint32_t row = wn * 64 + j * 16 + (lane & 7) + ((lane >> 4) & 1) * 8;
        bR[j]  = row * 128;
        bSX[j] = (bR[j] >> 3) & 0x70;
    }

    // fragment loader / mma block
    Frag f0, f1;
    auto load_frags = [&](Frag& f, uint32_t aS, uint32_t bS, uint32_t ck) {
        #pragma unroll
        for (int mi = 0; mi < 4; mi++)
            ldsm_x4(f.a[mi], aS + aR[mi] + ((ck | aQ) ^ aSX[mi]));
        #pragma unroll
        for (int j = 0; j < 4; j++)
            ldsm_x4(f.b[j], bS + bR[j] + ((ck | bQ) ^ bSX[j]));
    };

    float c[4][8][4];
    #pragma unroll
    for (int mi = 0; mi < 4; mi++)
        #pragma unroll
        for (int nj = 0; nj < 8; nj++)
            #pragma unroll
            for (int k = 0; k < 4; k++) c[mi][nj][k] = 0.f;

    auto mma_block = [&](const Frag& f) {
        #pragma unroll
        for (int mi = 0; mi < 4; mi++)
            #pragma unroll
            for (int nj = 0; nj < 8; nj++)
                mma16816(c[mi][nj], f.a[mi], &f.b[nj >> 1][(nj & 1) * 2]);
    };

    // consumer prologue: wait stage 0, load kk=0 frags
    mbar_wait(sb + 0, 0u);
    load_frags(f0, sb + SM_STAGE0, sb + SM_STAGE0 + A_ST, 0);

    // ---- main loop ----
    for (int it = 0; it < ITERS; ++it) {
        int s = it % DEPTH;
        if (tid == 0 && it + DEPTH - 1 < ITERS) {
            int blk = it + DEPTH - 1, ss = blk % DEPTH;
            int v = blk / DEPTH;                 // reuse count of stage ss
            if (v >= 1)
                mbar_wait_relaxed(sb + 16 * ss + 8, (uint32_t)((v - 1) & 1));
            mbar_expect_tx(sb + 16 * ss, STAGE);
            uint32_t dst = sb + SM_STAGE0 + ss * STAGE;
            tma2d(dst, pa, blk * KC, m0, sb + 16 * ss);
            tma2d(dst + A_ST, pb, blk * KC, n0, sb + 16 * ss);
        }

        const uint32_t aS = sb + SM_STAGE0 + s * STAGE;
        const uint32_t bS = aS + A_ST;
        load_frags(f1, aS, bS, 32);    // kk=1
        mma_block(f0);                 // kk=0
        load_frags(f0, aS, bS, 64);    // kk=2
        mma_block(f1);                 // kk=1
        load_frags(f1, aS, bS, 96);    // kk=3
        mma_block(f0);                 // kk=2
        // all smem reads of stage s issued -> release buffer
        if (lane == 0) mbar_arrive(sb + 16 * s + 8);
        mma_block(f1);                 // kk=3 (32 MMAs queue in tensor pipe)

        if (it + 1 < ITERS) {
            // cross-stage: wait + first LDSM hidden behind the MMA queue
            int s2 = (it + 1) % DEPTH;
            mbar_wait(sb + 16 * s2, (uint32_t)(((it + 1) / DEPTH) & 1));
            uint32_t aS2 = sb + SM_STAGE0 + s2 * STAGE;
            load_frags(f0, aS2, aS2 + A_ST, 0);
        }
    }

    // ---- epilogue: bias + direct float2 stores ----
    const int cbase = n0 + wn * 64 + (lane & 3) * 2;
    #pragma unroll
    for (int nj = 0; nj < 8; nj++) {
        const int col = cbase + nj * 8;
        const float2 bv = *reinterpret_cast<const float2*>(&bias[col]);
        #pragma unroll
        for (int mi = 0; mi < 4; mi++) {
            const int row = m0 + wm * 64 + mi * 16 + (lane >> 2);
            float2 v0 = {c[mi][nj][0] + bv.x, c[mi][nj][1] + bv.y};
            float2 v1 = {c[mi][nj][2] + bv.x, c[mi][nj][3] + bv.y};
            *reinterpret_cast<float2*>(&out[(size_t)row * NN + col])       = v0;
            *reinterpret_cast<float2*>(&out[(size_t)(row + 8) * NN + col]) = v1;
        }
    }
}

// ---------------------------------------------------------------------------
// Host launcher
// ---------------------------------------------------------------------------
typedef CUresult (*PFN_encodeTiled)(CUtensorMap*, CUtensorMapDataType, cuuint32_t, void*,
                                    const cuuint64_t*, const cuuint64_t*, const cuuint32_t*,
                                    const cuuint32_t*, CUtensorMapInterleave, CUtensorMapSwizzle,
                                    CUtensorMapL2promotion, CUtensorMapFloatOOBfill);

extern "C" void kernel_launch(void* const* d_in, const int* in_sizes, int n_in,
                              void* d_out, int out_size) {
    if (n_in < 3) return;
    const float* x    = (const float*)d_in[0];
    const float* W    = (const float*)d_in[1];
    const float* bias = (const float*)d_in[2];
    float* out = (float*)d_out;

    void* pA = nullptr;
    void* pB = nullptr;
    cudaGetSymbolAddress(&pA, g_xq);
    cudaGetSymbolAddress(&pB, g_wq);

    // 1) fused fp8 roundtrip -> fp16 scratch (16 elems/thread, one launch)
    {
        int nx16 = (int)(((long long)MM * KK) / 16);   // 2097152
        int nw16 = (int)(((long long)NN * KK) / 16);   // 1048576
        int total = nx16 + nw16;
        quant_deq_fused<<<(total + 255) / 256, 256>>>(x, (__half*)pA, nx16,
                                                      W, (__half*)pB, nw16);
    }

    // 2) TMA descriptors via driver entry point (no -lcuda)
    void* fn = nullptr;
    cudaDriverEntryPointQueryResult qr;
    cudaGetDriverEntryPointByVersion("cuTensorMapEncodeTiled", &fn, 12000,
                                     cudaEnableDefault, &qr);
    if (!fn) return;
    PFN_encodeTiled encode = (PFN_encodeTiled)fn;

    CUtensorMap map_a, map_b;
    {
        cuuint64_t dims[2]    = {(cuuint64_t)KK, (cuuint64_t)MM};
        cuuint64_t strides[1] = {(cuuint64_t)KK * 2};
        cuuint32_t box[2]     = {(cuuint32_t)KC, (cuuint32_t)TILE_M};
        cuuint32_t es[2]      = {1, 1};
        if (encode(&map_a, CU_TENSOR_MAP_DATA_TYPE_FLOAT16, 2, pA, dims, strides, box, es,
                   CU_TENSOR_MAP_INTERLEAVE_NONE, CU_TENSOR_MAP_SWIZZLE_128B,
                   CU_TENSOR_MAP_L2_PROMOTION_L2_128B,
                   CU_TENSOR_MAP_FLOAT_OOB_FILL_NONE) != CUDA_SUCCESS)
            return;
    }
    {
        cuuint64_t dims[2]    = {(cuuint64_t)KK, (cuuint64_t)NN};
        cuuint64_t strides[1] = {(cuuint64_t)KK * 2};
        cuuint32_t box[2]     = {(cuuint32_t)KC, (cuuint32_t)TILE_N};
        cuuint32_t es[2]      = {1, 1};
        if (encode(&map_b, CU_TENSOR_MAP_DATA_TYPE_FLOAT16, 2, pB, dims, strides, box, es,
                   CU_TENSOR_MAP_INTERLEAVE_NONE, CU_TENSOR_MAP_SWIZZLE_128B,
                   CU_TENSOR_MAP_L2_PROMOTION_L2_128B,
                   CU_TENSOR_MAP_FLOAT_OOB_FILL_NONE) != CUDA_SUCCESS)
            return;
    }

    // 3) GEMM
    cudaFuncSetAttribute(gemm_hmma_kernel, cudaFuncAttributeMaxDynamicSharedMemorySize,
                         SMEM_BYTES);
    int grid = (MM / TILE_M) * (NN / TILE_N);   // 1024
    gemm_hmma_kernel<<<grid, 256, SMEM_BYTES>>>(map_a, map_b, bias, out);
    (void)in_sizes; (void)out_size;
}